// round 15
// baseline (speedup 1.0000x reference)
#include <cuda_runtime.h>
#include <math.h>
#include <stdint.h>

#define DIM 1024
#define NSK 50
#define KBIG (NSK * DIM)   // 51200

// ---------------------------------------------------------------------------
// Device-global scratch (no allocations allowed)
// ---------------------------------------------------------------------------
__device__ float g_H[(size_t)4096 * KBIG];          // gate-weighted relu(x@W1+b1), tf32-rounded
__device__ float g_gates[(size_t)4096 * NSK];
__device__ float g_xr[(size_t)4096 * DIM];          // tf32-rounded x
__device__ float g_W1r[(size_t)NSK * DIM * DIM];    // tf32-rounded W1
__device__ float g_W2r[(size_t)NSK * DIM * DIM];    // tf32-rounded W2

// ---------------------------------------------------------------------------
// Helpers
// ---------------------------------------------------------------------------
__device__ __forceinline__ float to_tf32(float x) {
    uint32_t u;
    asm("cvt.rna.tf32.f32 %0, %1;" : "=r"(u) : "f"(x));
    return __uint_as_float(u);
}

__device__ __forceinline__ void cpa16(void* s, const void* g) {
    uint32_t sa = (uint32_t)__cvta_generic_to_shared(s);
    asm volatile("cp.async.cg.shared.global [%0], [%1], 16;" :: "r"(sa), "l"(g));
}
__device__ __forceinline__ void cpa_commit() { asm volatile("cp.async.commit_group;"); }
template<int N> __device__ __forceinline__ void cpa_wait() {
    asm volatile("cp.async.wait_group %0;" :: "n"(N));
}

// m16n8k8 tf32 MMA. Fragment maps (g=lane>>2, t=lane&3):
//   A: a0=(g,t) a1=(g+8,t) a2=(g,t+4) a3=(g+8,t+4)
//   B: b0=(t,n=g) b1=(t+4,n=g)
//   C: c0=(g,2t) c1=(g,2t+1) c2=(g+8,2t) c3=(g+8,2t+1)
__device__ __forceinline__ void mma8(float* c, const uint32_t* a, const uint32_t* b) {
    asm volatile(
        "mma.sync.aligned.m16n8k8.row.col.f32.tf32.tf32.f32 "
        "{%0,%1,%2,%3},{%4,%5,%6,%7},{%8,%9},{%0,%1,%2,%3};"
        : "+f"(c[0]), "+f"(c[1]), "+f"(c[2]), "+f"(c[3])
        : "r"(a[0]), "r"(a[1]), "r"(a[2]), "r"(a[3]), "r"(b[0]), "r"(b[1]));
}

// ---------------------------------------------------------------------------
// tf32 rounding prep:  which: 0 -> g_xr, 1 -> g_W1r, 2 -> g_W2r
// ---------------------------------------------------------------------------
__global__ __launch_bounds__(256) void round_kernel(const float4* __restrict__ in,
                                                    int which, int n4) {
    float4* out = (which == 0) ? (float4*)g_xr
                : (which == 1) ? (float4*)g_W1r
                               : (float4*)g_W2r;
    for (int i = blockIdx.x * blockDim.x + threadIdx.x; i < n4;
         i += gridDim.x * blockDim.x) {
        float4 v = in[i];
        v.x = to_tf32(v.x); v.y = to_tf32(v.y);
        v.z = to_tf32(v.z); v.w = to_tf32(v.w);
        out[i] = v;
    }
}

// ---------------------------------------------------------------------------
// Gating: logits GEMM (smem-staged Wg) + fused softmax.
// Block = 8 tokens, warp per token. grid = M/8.
// ---------------------------------------------------------------------------
__global__ __launch_bounds__(256) void gate_kernel(const float* __restrict__ x,
                                                   const float* __restrict__ Wg,
                                                   const float* __restrict__ bg) {
    __shared__ float xs[8][DIM];      // 32 KB
    __shared__ float ws[32][64];      // 8 KB (cols >= NSK zero-filled)

    int tid = threadIdx.x, lane = tid & 31, w = tid >> 5;
    int tok0 = blockIdx.x * 8;

    const float4* xg = reinterpret_cast<const float4*>(x + (size_t)tok0 * DIM);
    float4* xs4 = reinterpret_cast<float4*>(&xs[0][0]);
    for (int i = tid; i < 8 * DIM / 4; i += 256) xs4[i] = xg[i];

    float acc0 = 0.f, acc1 = 0.f;
    for (int k0 = 0; k0 < DIM; k0 += 32) {
        __syncthreads();
        for (int i = tid; i < 32 * 64; i += 256) {
            int r = i >> 6, c = i & 63;
            ws[r][c] = (c < NSK) ? Wg[(size_t)(k0 + r) * NSK + c] : 0.f;
        }
        __syncthreads();
        #pragma unroll
        for (int kk = 0; kk < 32; ++kk) {
            float xv = xs[w][k0 + kk];                 // broadcast
            acc0 = fmaf(xv, ws[kk][lane], acc0);       // conflict-free
            acc1 = fmaf(xv, ws[kk][32 + lane], acc1);
        }
    }

    float l0 = acc0 + bg[lane];
    float l1 = (lane < NSK - 32) ? (acc1 + bg[32 + lane]) : -1e30f;
    float mx = fmaxf(l0, l1);
    #pragma unroll
    for (int o = 16; o > 0; o >>= 1) mx = fmaxf(mx, __shfl_xor_sync(~0u, mx, o));
    float p0 = expf(l0 - mx);
    float p1 = (lane < NSK - 32) ? expf(l1 - mx) : 0.f;
    float s = p0 + p1;
    #pragma unroll
    for (int o = 16; o > 0; o >>= 1) s += __shfl_xor_sync(~0u, s, o);
    float inv = 1.f / s;

    int tok = tok0 + w;
    g_gates[(size_t)tok * NSK + lane] = p0 * inv;
    if (lane < NSK - 32) g_gates[(size_t)tok * NSK + 32 + lane] = p1 * inv;
}

// ---------------------------------------------------------------------------
// out init: out[m,n] = sum_e gates[m,e] * b2[e,n]
// ---------------------------------------------------------------------------
__global__ __launch_bounds__(256) void outinit_kernel(const float* __restrict__ b2,
                                                      float* __restrict__ out, int total) {
    int idx = blockIdx.x * 256 + threadIdx.x;
    if (idx >= total) return;
    int m = idx >> 10, n = idx & (DIM - 1);
    const float* gr = &g_gates[(size_t)m * NSK];
    float a = 0.f;
    #pragma unroll
    for (int e = 0; e < NSK; e++)
        a = fmaf(gr[e], b2[(size_t)e * DIM + n], a);   // gr broadcast, b2 coalesced
    out[idx] = a;
}

// ---------------------------------------------------------------------------
// tf32 MMA GEMM: BM=128 BN=128 BK=16, 2-stage cp.async, 8 warps (4m x 2n),
// warp tile 32x64 (2 m-tiles x 8 n-tiles of m16n8k8).
//   G1 (per-expert, grid.z=e):  Hg[m, e*D+n] = tf32(gate * relu(x@W1[e] + b1[e]))
//   G2 (monolithic):            out[m,n]    += Hg @ W2flat
// ---------------------------------------------------------------------------
template<int KDIM, bool G1>
__global__ __launch_bounds__(256, 2) void mma_gemm(const float* __restrict__ b1all,
                                                   float* __restrict__ out) {
    __shared__ float As[2][128][20];   // 16 k-floats + pad 4  (bank-clean: (20m+t)%32)
    __shared__ float Bs[2][16][136];   // 128 n-floats + pad 8 (bank-clean: 8t+g)

    const int tid  = threadIdx.x;
    const int lane = tid & 31;
    const int wid  = tid >> 5;
    const int g    = lane >> 2, t = lane & 3;
    const int wm   = wid & 3,  wn = wid >> 2;
    const int m0 = blockIdx.y * 128, n0 = blockIdx.x * 128;
    const int e  = G1 ? blockIdx.z : 0;

    const float* A = G1 ? g_xr : g_H;
    const float* B = G1 ? (g_W1r + (size_t)e * DIM * DIM) : g_W2r;
    const int lda = KDIM, ldb = DIM;

    const int am = tid >> 2, aq = tid & 3;    // A loader: rows am, am+64; quad aq
    const int br = tid >> 4, bq = tid & 15;   // B loader: row br; quads bq, bq+16

    float acc[2][8][4];
    #pragma unroll
    for (int i = 0; i < 2; i++)
        #pragma unroll
        for (int j = 0; j < 8; j++)
            #pragma unroll
            for (int q = 0; q < 4; q++) acc[i][j][q] = 0.f;

    auto load_stage = [&](int s, int k0) {
        cpa16(&As[s][am][aq * 4],        A + (size_t)(m0 + am) * lda + k0 + aq * 4);
        cpa16(&As[s][am + 64][aq * 4],   A + (size_t)(m0 + am + 64) * lda + k0 + aq * 4);
        cpa16(&Bs[s][br][bq * 4],        B + (size_t)(k0 + br) * ldb + n0 + bq * 4);
        cpa16(&Bs[s][br][(bq + 16) * 4], B + (size_t)(k0 + br) * ldb + n0 + (bq + 16) * 4);
        cpa_commit();
    };

    const int NIT = KDIM / 16;
    load_stage(0, 0);

    for (int it = 0; it < NIT; ++it) {
        if (it + 1 < NIT) {
            load_stage((it + 1) & 1, (it + 1) * 16);
            cpa_wait<1>();
        } else {
            cpa_wait<0>();
        }
        __syncthreads();

        int s = it & 1;
        const uint32_t* Au = reinterpret_cast<const uint32_t*>(&As[s][0][0]);
        const uint32_t* Bu = reinterpret_cast<const uint32_t*>(&Bs[s][0][0]);

        #pragma unroll
        for (int k8 = 0; k8 < 2; ++k8) {
            const int kb = k8 * 8;
            uint32_t af[2][4];
            #pragma unroll
            for (int mt = 0; mt < 2; ++mt) {
                int r = wm * 32 + mt * 16 + g;
                af[mt][0] = Au[(r    ) * 20 + kb + t];
                af[mt][1] = Au[(r + 8) * 20 + kb + t];
                af[mt][2] = Au[(r    ) * 20 + kb + t + 4];
                af[mt][3] = Au[(r + 8) * 20 + kb + t + 4];
            }
            uint32_t bf[8][2];
            #pragma unroll
            for (int nt = 0; nt < 8; ++nt) {
                int c = wn * 64 + nt * 8 + g;
                bf[nt][0] = Bu[(kb + t    ) * 136 + c];
                bf[nt][1] = Bu[(kb + t + 4) * 136 + c];
            }
            #pragma unroll
            for (int mt = 0; mt < 2; ++mt)
                #pragma unroll
                for (int nt = 0; nt < 8; ++nt)
                    mma8(acc[mt][nt], af[mt], bf[nt]);
        }
        __syncthreads();
    }

    // ---- epilogue ----
    if (G1) {
        #pragma unroll
        for (int mt = 0; mt < 2; ++mt) {
            int r = m0 + wm * 32 + mt * 16 + g;
            float ga = g_gates[(size_t)r * NSK + e];
            float gb = g_gates[(size_t)(r + 8) * NSK + e];
            #pragma unroll
            for (int nt = 0; nt < 8; ++nt) {
                int c = n0 + wn * 64 + nt * 8 + 2 * t;
                float ba = b1all[e * DIM + c];
                float bb = b1all[e * DIM + c + 1];
                float v00 = fmaxf(acc[mt][nt][0] + ba, 0.f) * ga;
                float v01 = fmaxf(acc[mt][nt][1] + bb, 0.f) * ga;
                float v10 = fmaxf(acc[mt][nt][2] + ba, 0.f) * gb;
                float v11 = fmaxf(acc[mt][nt][3] + bb, 0.f) * gb;
                *reinterpret_cast<float2*>(&g_H[(size_t)r * KBIG + (size_t)e * DIM + c]) =
                    make_float2(to_tf32(v00), to_tf32(v01));
                *reinterpret_cast<float2*>(&g_H[(size_t)(r + 8) * KBIG + (size_t)e * DIM + c]) =
                    make_float2(to_tf32(v10), to_tf32(v11));
            }
        }
    } else {
        #pragma unroll
        for (int mt = 0; mt < 2; ++mt) {
            int r = m0 + wm * 32 + mt * 16 + g;
            #pragma unroll
            for (int nt = 0; nt < 8; ++nt) {
                int c = n0 + wn * 64 + nt * 8 + 2 * t;
                float2* p0 = reinterpret_cast<float2*>(&out[(size_t)r * DIM + c]);
                float2* p1 = reinterpret_cast<float2*>(&out[(size_t)(r + 8) * DIM + c]);
                float2 v0 = *p0, v1 = *p1;
                v0.x += acc[mt][nt][0]; v0.y += acc[mt][nt][1];
                v1.x += acc[mt][nt][2]; v1.y += acc[mt][nt][3];
                *p0 = v0; *p1 = v1;
            }
        }
    }
}

// ---------------------------------------------------------------------------
extern "C" void kernel_launch(void* const* d_in, const int* in_sizes, int n_in,
                              void* d_out, int out_size) {
    const float* x  = (const float*)d_in[0];
    const float* W1 = (const float*)d_in[1];
    const float* b1 = (const float*)d_in[2];
    const float* W2 = (const float*)d_in[3];
    const float* b2 = (const float*)d_in[4];
    const float* Wg = (const float*)d_in[5];
    const float* bg = (const float*)d_in[6];
    float* out = (float*)d_out;

    int M = in_sizes[0] / DIM;   // 4096

    // tf32-round the MMA operands into device-global copies
    round_kernel<<<2048, 256>>>((const float4*)x,  0, M * DIM / 4);
    round_kernel<<<8192, 256>>>((const float4*)W1, 1, NSK * DIM * DIM / 4);
    round_kernel<<<8192, 256>>>((const float4*)W2, 2, NSK * DIM * DIM / 4);

    gate_kernel<<<M / 8, 256>>>(x, Wg, bg);
    outinit_kernel<<<(M * DIM + 255) / 256, 256>>>(b2, out, M * DIM);

    mma_gemm<DIM,  true ><<<dim3(DIM / 128, M / 128, NSK), 256>>>(b1, nullptr);
    mma_gemm<KBIG, false><<<dim3(DIM / 128, M / 128),      256>>>(nullptr, out);
}

// round 16
// speedup vs baseline: 1.0008x; 1.0008x over previous
#include <cuda_runtime.h>
#include <math.h>
#include <stdint.h>

#define DIM 1024
#define NSK 50
#define KBIG (NSK * DIM)   // 51200

// ---------------------------------------------------------------------------
// Device-global scratch (no allocations allowed)
// ---------------------------------------------------------------------------
__device__ float g_H[(size_t)4096 * KBIG];          // gate-weighted relu(x@W1+b1), tf32-rounded
__device__ float g_gates[(size_t)4096 * NSK];
__device__ float g_xr[(size_t)4096 * DIM];          // tf32-rounded x
__device__ float g_W1r[(size_t)NSK * DIM * DIM];    // tf32-rounded W1
__device__ float g_W2r[(size_t)NSK * DIM * DIM];    // tf32-rounded W2

// ---------------------------------------------------------------------------
// Helpers
// ---------------------------------------------------------------------------
__device__ __forceinline__ float to_tf32(float x) {
    uint32_t u;
    asm("cvt.rna.tf32.f32 %0, %1;" : "=r"(u) : "f"(x));
    return __uint_as_float(u);
}

__device__ __forceinline__ void cpa16(void* s, const void* g) {
    uint32_t sa = (uint32_t)__cvta_generic_to_shared(s);
    asm volatile("cp.async.cg.shared.global [%0], [%1], 16;" :: "r"(sa), "l"(g));
}
__device__ __forceinline__ void cpa_commit() { asm volatile("cp.async.commit_group;"); }
template<int N> __device__ __forceinline__ void cpa_wait() {
    asm volatile("cp.async.wait_group %0;" :: "n"(N));
}

// m16n8k8 tf32 MMA. Fragment maps (g=lane>>2, t=lane&3):
//   A: a0=(g,t) a1=(g+8,t) a2=(g,t+4) a3=(g+8,t+4)
//   B: b0=(t,n=g) b1=(t+4,n=g)
//   C: c0=(g,2t) c1=(g,2t+1) c2=(g+8,2t) c3=(g+8,2t+1)
__device__ __forceinline__ void mma8(float* c, const uint32_t* a, const uint32_t* b) {
    asm volatile(
        "mma.sync.aligned.m16n8k8.row.col.f32.tf32.tf32.f32 "
        "{%0,%1,%2,%3},{%4,%5,%6,%7},{%8,%9},{%0,%1,%2,%3};"
        : "+f"(c[0]), "+f"(c[1]), "+f"(c[2]), "+f"(c[3])
        : "r"(a[0]), "r"(a[1]), "r"(a[2]), "r"(a[3]), "r"(b[0]), "r"(b[1]));
}

// ---------------------------------------------------------------------------
// tf32 rounding prep:  which: 0 -> g_xr, 1 -> g_W1r, 2 -> g_W2r
// ---------------------------------------------------------------------------
__global__ __launch_bounds__(256) void round_kernel(const float4* __restrict__ in,
                                                    int which, int n4) {
    float4* out = (which == 0) ? (float4*)g_xr
                : (which == 1) ? (float4*)g_W1r
                               : (float4*)g_W2r;
    for (int i = blockIdx.x * blockDim.x + threadIdx.x; i < n4;
         i += gridDim.x * blockDim.x) {
        float4 v = in[i];
        v.x = to_tf32(v.x); v.y = to_tf32(v.y);
        v.z = to_tf32(v.z); v.w = to_tf32(v.w);
        out[i] = v;
    }
}

// ---------------------------------------------------------------------------
// Gating: logits GEMM (smem-staged Wg) + fused softmax.
// Block = 8 tokens, warp per token. grid = M/8.
// ---------------------------------------------------------------------------
__global__ __launch_bounds__(256) void gate_kernel(const float* __restrict__ x,
                                                   const float* __restrict__ Wg,
                                                   const float* __restrict__ bg) {
    __shared__ float xs[8][DIM];      // 32 KB
    __shared__ float ws[32][64];      // 8 KB (cols >= NSK zero-filled)

    int tid = threadIdx.x, lane = tid & 31, w = tid >> 5;
    int tok0 = blockIdx.x * 8;

    const float4* xg = reinterpret_cast<const float4*>(x + (size_t)tok0 * DIM);
    float4* xs4 = reinterpret_cast<float4*>(&xs[0][0]);
    for (int i = tid; i < 8 * DIM / 4; i += 256) xs4[i] = xg[i];

    float acc0 = 0.f, acc1 = 0.f;
    for (int k0 = 0; k0 < DIM; k0 += 32) {
        __syncthreads();
        for (int i = tid; i < 32 * 64; i += 256) {
            int r = i >> 6, c = i & 63;
            ws[r][c] = (c < NSK) ? Wg[(size_t)(k0 + r) * NSK + c] : 0.f;
        }
        __syncthreads();
        #pragma unroll
        for (int kk = 0; kk < 32; ++kk) {
            float xv = xs[w][k0 + kk];                 // broadcast
            acc0 = fmaf(xv, ws[kk][lane], acc0);       // conflict-free
            acc1 = fmaf(xv, ws[kk][32 + lane], acc1);
        }
    }

    float l0 = acc0 + bg[lane];
    float l1 = (lane < NSK - 32) ? (acc1 + bg[32 + lane]) : -1e30f;
    float mx = fmaxf(l0, l1);
    #pragma unroll
    for (int o = 16; o > 0; o >>= 1) mx = fmaxf(mx, __shfl_xor_sync(~0u, mx, o));
    float p0 = expf(l0 - mx);
    float p1 = (lane < NSK - 32) ? expf(l1 - mx) : 0.f;
    float s = p0 + p1;
    #pragma unroll
    for (int o = 16; o > 0; o >>= 1) s += __shfl_xor_sync(~0u, s, o);
    float inv = 1.f / s;

    int tok = tok0 + w;
    g_gates[(size_t)tok * NSK + lane] = p0 * inv;
    if (lane < NSK - 32) g_gates[(size_t)tok * NSK + 32 + lane] = p1 * inv;
}

// ---------------------------------------------------------------------------
// out init: out[m,n] = sum_e gates[m,e] * b2[e,n]
// ---------------------------------------------------------------------------
__global__ __launch_bounds__(256) void outinit_kernel(const float* __restrict__ b2,
                                                      float* __restrict__ out, int total) {
    int idx = blockIdx.x * 256 + threadIdx.x;
    if (idx >= total) return;
    int m = idx >> 10, n = idx & (DIM - 1);
    const float* gr = &g_gates[(size_t)m * NSK];
    float a = 0.f;
    #pragma unroll
    for (int e = 0; e < NSK; e++)
        a = fmaf(gr[e], b2[(size_t)e * DIM + n], a);   // gr broadcast, b2 coalesced
    out[idx] = a;
}

// ---------------------------------------------------------------------------
// tf32 MMA GEMM: BM=128 BN=128 BK=16, 2-stage cp.async, 8 warps (4m x 2n),
// warp tile 32x64 (2 m-tiles x 8 n-tiles of m16n8k8).
//   G1 (per-expert, grid.z=e):  Hg[m, e*D+n] = tf32(gate * relu(x@W1[e] + b1[e]))
//   G2 (monolithic):            out[m,n]    += Hg @ W2flat
// ---------------------------------------------------------------------------
template<int KDIM, bool G1>
__global__ __launch_bounds__(256, 2) void mma_gemm(const float* __restrict__ b1all,
                                                   float* __restrict__ out) {
    __shared__ float As[2][128][20];   // 16 k-floats + pad 4  (bank-clean: (20m+t)%32)
    __shared__ float Bs[2][16][136];   // 128 n-floats + pad 8 (bank-clean: 8t+g)

    const int tid  = threadIdx.x;
    const int lane = tid & 31;
    const int wid  = tid >> 5;
    const int g    = lane >> 2, t = lane & 3;
    const int wm   = wid & 3,  wn = wid >> 2;
    const int m0 = blockIdx.y * 128, n0 = blockIdx.x * 128;
    const int e  = G1 ? blockIdx.z : 0;

    const float* A = G1 ? g_xr : g_H;
    const float* B = G1 ? (g_W1r + (size_t)e * DIM * DIM) : g_W2r;
    const int lda = KDIM, ldb = DIM;

    const int am = tid >> 2, aq = tid & 3;    // A loader: rows am, am+64; quad aq
    const int br = tid >> 4, bq = tid & 15;   // B loader: row br; quads bq, bq+16

    float acc[2][8][4];
    #pragma unroll
    for (int i = 0; i < 2; i++)
        #pragma unroll
        for (int j = 0; j < 8; j++)
            #pragma unroll
            for (int q = 0; q < 4; q++) acc[i][j][q] = 0.f;

    auto load_stage = [&](int s, int k0) {
        cpa16(&As[s][am][aq * 4],        A + (size_t)(m0 + am) * lda + k0 + aq * 4);
        cpa16(&As[s][am + 64][aq * 4],   A + (size_t)(m0 + am + 64) * lda + k0 + aq * 4);
        cpa16(&Bs[s][br][bq * 4],        B + (size_t)(k0 + br) * ldb + n0 + bq * 4);
        cpa16(&Bs[s][br][(bq + 16) * 4], B + (size_t)(k0 + br) * ldb + n0 + (bq + 16) * 4);
        cpa_commit();
    };

    const int NIT = KDIM / 16;
    load_stage(0, 0);

    for (int it = 0; it < NIT; ++it) {
        if (it + 1 < NIT) {
            load_stage((it + 1) & 1, (it + 1) * 16);
            cpa_wait<1>();
        } else {
            cpa_wait<0>();
        }
        __syncthreads();

        int s = it & 1;
        const uint32_t* Au = reinterpret_cast<const uint32_t*>(&As[s][0][0]);
        const uint32_t* Bu = reinterpret_cast<const uint32_t*>(&Bs[s][0][0]);

        #pragma unroll
        for (int k8 = 0; k8 < 2; ++k8) {
            const int kb = k8 * 8;
            uint32_t af[2][4];
            #pragma unroll
            for (int mt = 0; mt < 2; ++mt) {
                int r = wm * 32 + mt * 16 + g;
                af[mt][0] = Au[(r    ) * 20 + kb + t];
                af[mt][1] = Au[(r + 8) * 20 + kb + t];
                af[mt][2] = Au[(r    ) * 20 + kb + t + 4];
                af[mt][3] = Au[(r + 8) * 20 + kb + t + 4];
            }
            uint32_t bf[8][2];
            #pragma unroll
            for (int nt = 0; nt < 8; ++nt) {
                int c = wn * 64 + nt * 8 + g;
                bf[nt][0] = Bu[(kb + t    ) * 136 + c];
                bf[nt][1] = Bu[(kb + t + 4) * 136 + c];
            }
            #pragma unroll
            for (int mt = 0; mt < 2; ++mt)
                #pragma unroll
                for (int nt = 0; nt < 8; ++nt)
                    mma8(acc[mt][nt], af[mt], bf[nt]);
        }
        __syncthreads();
    }

    // ---- epilogue ----
    if (G1) {
        #pragma unroll
        for (int mt = 0; mt < 2; ++mt) {
            int r = m0 + wm * 32 + mt * 16 + g;
            float ga = g_gates[(size_t)r * NSK + e];
            float gb = g_gates[(size_t)(r + 8) * NSK + e];
            #pragma unroll
            for (int nt = 0; nt < 8; ++nt) {
                int c = n0 + wn * 64 + nt * 8 + 2 * t;
                float ba = b1all[e * DIM + c];
                float bb = b1all[e * DIM + c + 1];
                float v00 = fmaxf(acc[mt][nt][0] + ba, 0.f) * ga;
                float v01 = fmaxf(acc[mt][nt][1] + bb, 0.f) * ga;
                float v10 = fmaxf(acc[mt][nt][2] + ba, 0.f) * gb;
                float v11 = fmaxf(acc[mt][nt][3] + bb, 0.f) * gb;
                *reinterpret_cast<float2*>(&g_H[(size_t)r * KBIG + (size_t)e * DIM + c]) =
                    make_float2(to_tf32(v00), to_tf32(v01));
                *reinterpret_cast<float2*>(&g_H[(size_t)(r + 8) * KBIG + (size_t)e * DIM + c]) =
                    make_float2(to_tf32(v10), to_tf32(v11));
            }
        }
    } else {
        #pragma unroll
        for (int mt = 0; mt < 2; ++mt) {
            int r = m0 + wm * 32 + mt * 16 + g;
            #pragma unroll
            for (int nt = 0; nt < 8; ++nt) {
                int c = n0 + wn * 64 + nt * 8 + 2 * t;
                float2* p0 = reinterpret_cast<float2*>(&out[(size_t)r * DIM + c]);
                float2* p1 = reinterpret_cast<float2*>(&out[(size_t)(r + 8) * DIM + c]);
                float2 v0 = *p0, v1 = *p1;
                v0.x += acc[mt][nt][0]; v0.y += acc[mt][nt][1];
                v1.x += acc[mt][nt][2]; v1.y += acc[mt][nt][3];
                *p0 = v0; *p1 = v1;
            }
        }
    }
}

// ---------------------------------------------------------------------------
extern "C" void kernel_launch(void* const* d_in, const int* in_sizes, int n_in,
                              void* d_out, int out_size) {
    const float* x  = (const float*)d_in[0];
    const float* W1 = (const float*)d_in[1];
    const float* b1 = (const float*)d_in[2];
    const float* W2 = (const float*)d_in[3];
    const float* b2 = (const float*)d_in[4];
    const float* Wg = (const float*)d_in[5];
    const float* bg = (const float*)d_in[6];
    float* out = (float*)d_out;

    int M = in_sizes[0] / DIM;   // 4096

    // tf32-round the MMA operands into device-global copies
    round_kernel<<<2048, 256>>>((const float4*)x,  0, M * DIM / 4);
    round_kernel<<<8192, 256>>>((const float4*)W1, 1, NSK * DIM * DIM / 4);
    round_kernel<<<8192, 256>>>((const float4*)W2, 2, NSK * DIM * DIM / 4);

    gate_kernel<<<M / 8, 256>>>(x, Wg, bg);
    outinit_kernel<<<(M * DIM + 255) / 256, 256>>>(b2, out, M * DIM);

    mma_gemm<DIM,  true ><<<dim3(DIM / 128, M / 128, NSK), 256>>>(b1, nullptr);
    mma_gemm<KBIG, false><<<dim3(DIM / 128, M / 128),      256>>>(nullptr, out);
}

// round 17
// speedup vs baseline: 1.0011x; 1.0003x over previous
#include <cuda_runtime.h>
#include <math.h>
#include <stdint.h>

#define DIM 1024
#define NSK 50
#define KBIG (NSK * DIM)   // 51200

// ---------------------------------------------------------------------------
// Device-global scratch (no allocations allowed)
// ---------------------------------------------------------------------------
__device__ float g_H[(size_t)4096 * KBIG];          // gate-weighted relu(x@W1+b1), tf32-rounded
__device__ float g_gates[(size_t)4096 * NSK];
__device__ float g_xr[(size_t)4096 * DIM];          // tf32-rounded x
__device__ float g_W1r[(size_t)NSK * DIM * DIM];    // tf32-rounded W1
__device__ float g_W2r[(size_t)NSK * DIM * DIM];    // tf32-rounded W2

// ---------------------------------------------------------------------------
// Helpers
// ---------------------------------------------------------------------------
__device__ __forceinline__ float to_tf32(float x) {
    uint32_t u;
    asm("cvt.rna.tf32.f32 %0, %1;" : "=r"(u) : "f"(x));
    return __uint_as_float(u);
}

__device__ __forceinline__ void cpa16(void* s, const void* g) {
    uint32_t sa = (uint32_t)__cvta_generic_to_shared(s);
    asm volatile("cp.async.cg.shared.global [%0], [%1], 16;" :: "r"(sa), "l"(g));
}
__device__ __forceinline__ void cpa_commit() { asm volatile("cp.async.commit_group;"); }
template<int N> __device__ __forceinline__ void cpa_wait() {
    asm volatile("cp.async.wait_group %0;" :: "n"(N));
}

// m16n8k8 tf32 MMA. Fragment maps (g=lane>>2, t=lane&3):
//   A: a0=(g,t) a1=(g+8,t) a2=(g,t+4) a3=(g+8,t+4)
//   B: b0=(t,n=g) b1=(t+4,n=g)
//   C: c0=(g,2t) c1=(g,2t+1) c2=(g+8,2t) c3=(g+8,2t+1)
__device__ __forceinline__ void mma8(float* c, const uint32_t* a, const uint32_t* b) {
    asm volatile(
        "mma.sync.aligned.m16n8k8.row.col.f32.tf32.tf32.f32 "
        "{%0,%1,%2,%3},{%4,%5,%6,%7},{%8,%9},{%0,%1,%2,%3};"
        : "+f"(c[0]), "+f"(c[1]), "+f"(c[2]), "+f"(c[3])
        : "r"(a[0]), "r"(a[1]), "r"(a[2]), "r"(a[3]), "r"(b[0]), "r"(b[1]));
}

// ---------------------------------------------------------------------------
// tf32 rounding prep:  which: 0 -> g_xr, 1 -> g_W1r, 2 -> g_W2r
// ---------------------------------------------------------------------------
__global__ __launch_bounds__(256) void round_kernel(const float4* __restrict__ in,
                                                    int which, int n4) {
    float4* out = (which == 0) ? (float4*)g_xr
                : (which == 1) ? (float4*)g_W1r
                               : (float4*)g_W2r;
    for (int i = blockIdx.x * blockDim.x + threadIdx.x; i < n4;
         i += gridDim.x * blockDim.x) {
        float4 v = in[i];
        v.x = to_tf32(v.x); v.y = to_tf32(v.y);
        v.z = to_tf32(v.z); v.w = to_tf32(v.w);
        out[i] = v;
    }
}

// ---------------------------------------------------------------------------
// Gating: logits GEMM (smem-staged Wg) + fused softmax.
// Block = 8 tokens, warp per token. grid = M/8.
// ---------------------------------------------------------------------------
__global__ __launch_bounds__(256) void gate_kernel(const float* __restrict__ x,
                                                   const float* __restrict__ Wg,
                                                   const float* __restrict__ bg) {
    __shared__ float xs[8][DIM];      // 32 KB
    __shared__ float ws[32][64];      // 8 KB (cols >= NSK zero-filled)

    int tid = threadIdx.x, lane = tid & 31, w = tid >> 5;
    int tok0 = blockIdx.x * 8;

    const float4* xg = reinterpret_cast<const float4*>(x + (size_t)tok0 * DIM);
    float4* xs4 = reinterpret_cast<float4*>(&xs[0][0]);
    for (int i = tid; i < 8 * DIM / 4; i += 256) xs4[i] = xg[i];

    float acc0 = 0.f, acc1 = 0.f;
    for (int k0 = 0; k0 < DIM; k0 += 32) {
        __syncthreads();
        for (int i = tid; i < 32 * 64; i += 256) {
            int r = i >> 6, c = i & 63;
            ws[r][c] = (c < NSK) ? Wg[(size_t)(k0 + r) * NSK + c] : 0.f;
        }
        __syncthreads();
        #pragma unroll
        for (int kk = 0; kk < 32; ++kk) {
            float xv = xs[w][k0 + kk];                 // broadcast
            acc0 = fmaf(xv, ws[kk][lane], acc0);       // conflict-free
            acc1 = fmaf(xv, ws[kk][32 + lane], acc1);
        }
    }

    float l0 = acc0 + bg[lane];
    float l1 = (lane < NSK - 32) ? (acc1 + bg[32 + lane]) : -1e30f;
    float mx = fmaxf(l0, l1);
    #pragma unroll
    for (int o = 16; o > 0; o >>= 1) mx = fmaxf(mx, __shfl_xor_sync(~0u, mx, o));
    float p0 = expf(l0 - mx);
    float p1 = (lane < NSK - 32) ? expf(l1 - mx) : 0.f;
    float s = p0 + p1;
    #pragma unroll
    for (int o = 16; o > 0; o >>= 1) s += __shfl_xor_sync(~0u, s, o);
    float inv = 1.f / s;

    int tok = tok0 + w;
    g_gates[(size_t)tok * NSK + lane] = p0 * inv;
    if (lane < NSK - 32) g_gates[(size_t)tok * NSK + 32 + lane] = p1 * inv;
}

// ---------------------------------------------------------------------------
// out init: out[m,n] = sum_e gates[m,e] * b2[e,n]
// ---------------------------------------------------------------------------
__global__ __launch_bounds__(256) void outinit_kernel(const float* __restrict__ b2,
                                                      float* __restrict__ out, int total) {
    int idx = blockIdx.x * 256 + threadIdx.x;
    if (idx >= total) return;
    int m = idx >> 10, n = idx & (DIM - 1);
    const float* gr = &g_gates[(size_t)m * NSK];
    float a = 0.f;
    #pragma unroll
    for (int e = 0; e < NSK; e++)
        a = fmaf(gr[e], b2[(size_t)e * DIM + n], a);   // gr broadcast, b2 coalesced
    out[idx] = a;
}

// ---------------------------------------------------------------------------
// tf32 MMA GEMM: BM=128 BN=128 BK=16, 2-stage cp.async, 8 warps (4m x 2n),
// warp tile 32x64 (2 m-tiles x 8 n-tiles of m16n8k8).
//   G1 (per-expert, grid.z=e):  Hg[m, e*D+n] = tf32(gate * relu(x@W1[e] + b1[e]))
//   G2 (monolithic):            out[m,n]    += Hg @ W2flat
// ---------------------------------------------------------------------------
template<int KDIM, bool G1>
__global__ __launch_bounds__(256, 2) void mma_gemm(const float* __restrict__ b1all,
                                                   float* __restrict__ out) {
    __shared__ float As[2][128][20];   // 16 k-floats + pad 4  (bank-clean: (20m+t)%32)
    __shared__ float Bs[2][16][136];   // 128 n-floats + pad 8 (bank-clean: 8t+g)

    const int tid  = threadIdx.x;
    const int lane = tid & 31;
    const int wid  = tid >> 5;
    const int g    = lane >> 2, t = lane & 3;
    const int wm   = wid & 3,  wn = wid >> 2;
    const int m0 = blockIdx.y * 128, n0 = blockIdx.x * 128;
    const int e  = G1 ? blockIdx.z : 0;

    const float* A = G1 ? g_xr : g_H;
    const float* B = G1 ? (g_W1r + (size_t)e * DIM * DIM) : g_W2r;
    const int lda = KDIM, ldb = DIM;

    const int am = tid >> 2, aq = tid & 3;    // A loader: rows am, am+64; quad aq
    const int br = tid >> 4, bq = tid & 15;   // B loader: row br; quads bq, bq+16

    float acc[2][8][4];
    #pragma unroll
    for (int i = 0; i < 2; i++)
        #pragma unroll
        for (int j = 0; j < 8; j++)
            #pragma unroll
            for (int q = 0; q < 4; q++) acc[i][j][q] = 0.f;

    auto load_stage = [&](int s, int k0) {
        cpa16(&As[s][am][aq * 4],        A + (size_t)(m0 + am) * lda + k0 + aq * 4);
        cpa16(&As[s][am + 64][aq * 4],   A + (size_t)(m0 + am + 64) * lda + k0 + aq * 4);
        cpa16(&Bs[s][br][bq * 4],        B + (size_t)(k0 + br) * ldb + n0 + bq * 4);
        cpa16(&Bs[s][br][(bq + 16) * 4], B + (size_t)(k0 + br) * ldb + n0 + (bq + 16) * 4);
        cpa_commit();
    };

    const int NIT = KDIM / 16;
    load_stage(0, 0);

    for (int it = 0; it < NIT; ++it) {
        if (it + 1 < NIT) {
            load_stage((it + 1) & 1, (it + 1) * 16);
            cpa_wait<1>();
        } else {
            cpa_wait<0>();
        }
        __syncthreads();

        int s = it & 1;
        const uint32_t* Au = reinterpret_cast<const uint32_t*>(&As[s][0][0]);
        const uint32_t* Bu = reinterpret_cast<const uint32_t*>(&Bs[s][0][0]);

        #pragma unroll
        for (int k8 = 0; k8 < 2; ++k8) {
            const int kb = k8 * 8;
            uint32_t af[2][4];
            #pragma unroll
            for (int mt = 0; mt < 2; ++mt) {
                int r = wm * 32 + mt * 16 + g;
                af[mt][0] = Au[(r    ) * 20 + kb + t];
                af[mt][1] = Au[(r + 8) * 20 + kb + t];
                af[mt][2] = Au[(r    ) * 20 + kb + t + 4];
                af[mt][3] = Au[(r + 8) * 20 + kb + t + 4];
            }
            uint32_t bf[8][2];
            #pragma unroll
            for (int nt = 0; nt < 8; ++nt) {
                int c = wn * 64 + nt * 8 + g;
                bf[nt][0] = Bu[(kb + t    ) * 136 + c];
                bf[nt][1] = Bu[(kb + t + 4) * 136 + c];
            }
            #pragma unroll
            for (int mt = 0; mt < 2; ++mt)
                #pragma unroll
                for (int nt = 0; nt < 8; ++nt)
                    mma8(acc[mt][nt], af[mt], bf[nt]);
        }
        __syncthreads();
    }

    // ---- epilogue ----
    if (G1) {
        #pragma unroll
        for (int mt = 0; mt < 2; ++mt) {
            int r = m0 + wm * 32 + mt * 16 + g;
            float ga = g_gates[(size_t)r * NSK + e];
            float gb = g_gates[(size_t)(r + 8) * NSK + e];
            #pragma unroll
            for (int nt = 0; nt < 8; ++nt) {
                int c = n0 + wn * 64 + nt * 8 + 2 * t;
                float ba = b1all[e * DIM + c];
                float bb = b1all[e * DIM + c + 1];
                float v00 = fmaxf(acc[mt][nt][0] + ba, 0.f) * ga;
                float v01 = fmaxf(acc[mt][nt][1] + bb, 0.f) * ga;
                float v10 = fmaxf(acc[mt][nt][2] + ba, 0.f) * gb;
                float v11 = fmaxf(acc[mt][nt][3] + bb, 0.f) * gb;
                *reinterpret_cast<float2*>(&g_H[(size_t)r * KBIG + (size_t)e * DIM + c]) =
                    make_float2(to_tf32(v00), to_tf32(v01));
                *reinterpret_cast<float2*>(&g_H[(size_t)(r + 8) * KBIG + (size_t)e * DIM + c]) =
                    make_float2(to_tf32(v10), to_tf32(v11));
            }
        }
    } else {
        #pragma unroll
        for (int mt = 0; mt < 2; ++mt) {
            int r = m0 + wm * 32 + mt * 16 + g;
            #pragma unroll
            for (int nt = 0; nt < 8; ++nt) {
                int c = n0 + wn * 64 + nt * 8 + 2 * t;
                float2* p0 = reinterpret_cast<float2*>(&out[(size_t)r * DIM + c]);
                float2* p1 = reinterpret_cast<float2*>(&out[(size_t)(r + 8) * DIM + c]);
                float2 v0 = *p0, v1 = *p1;
                v0.x += acc[mt][nt][0]; v0.y += acc[mt][nt][1];
                v1.x += acc[mt][nt][2]; v1.y += acc[mt][nt][3];
                *p0 = v0; *p1 = v1;
            }
        }
    }
}

// ---------------------------------------------------------------------------
extern "C" void kernel_launch(void* const* d_in, const int* in_sizes, int n_in,
                              void* d_out, int out_size) {
    const float* x  = (const float*)d_in[0];
    const float* W1 = (const float*)d_in[1];
    const float* b1 = (const float*)d_in[2];
    const float* W2 = (const float*)d_in[3];
    const float* b2 = (const float*)d_in[4];
    const float* Wg = (const float*)d_in[5];
    const float* bg = (const float*)d_in[6];
    float* out = (float*)d_out;

    int M = in_sizes[0] / DIM;   // 4096

    // tf32-round the MMA operands into device-global copies
    round_kernel<<<2048, 256>>>((const float4*)x,  0, M * DIM / 4);
    round_kernel<<<8192, 256>>>((const float4*)W1, 1, NSK * DIM * DIM / 4);
    round_kernel<<<8192, 256>>>((const float4*)W2, 2, NSK * DIM * DIM / 4);

    gate_kernel<<<M / 8, 256>>>(x, Wg, bg);
    outinit_kernel<<<(M * DIM + 255) / 256, 256>>>(b2, out, M * DIM);

    mma_gemm<DIM,  true ><<<dim3(DIM / 128, M / 128, NSK), 256>>>(b1, nullptr);
    mma_gemm<KBIG, false><<<dim3(DIM / 128, M / 128),      256>>>(nullptr, out);
}